// round 5
// baseline (speedup 1.0000x reference)
#include <cuda_runtime.h>

#define NN   35
#define D1   512
#define D2   256
#define D3   128
#define NS2  32
#define ICH2 (D1/NS2)   // 16
#define NS3  32
#define ICH3 (D2/NS3)   // 8
#define SXW  36         // smem row stride (35 entries + pad, even for ld64)

typedef unsigned long long ull;

__device__ float g_h1[NN*D1];
__device__ float g_h2[NN*D2];
__device__ float g_h3[NN*D3];
__device__ float g_p2[NS2][NN*D2];
__device__ float g_p3[NS3][NN*D3];

// COO is src-major, fully connected, no self-loops
__device__ __forceinline__ int edge_id(int s, int n) {
    return s*(NN-1) + (s < n ? n-1 : n);
}

// ---- packed f32x2 helpers ----
__device__ __forceinline__ ull fma2(ull a, ull b, ull c) {
    ull d;
    asm("fma.rn.f32x2 %0, %1, %2, %3;" : "=l"(d) : "l"(a), "l"(b), "l"(c));
    return d;
}
__device__ __forceinline__ ull pk2(float lo, float hi) {
    ull r; asm("mov.b64 %0, {%1,%2};" : "=l"(r) : "f"(lo), "f"(hi)); return r;
}
__device__ __forceinline__ void upk2(ull v, float& lo, float& hi) {
    asm("mov.b64 {%0,%1}, %2;" : "=f"(lo), "=f"(hi) : "l"(v));
}
__device__ __forceinline__ ull relu2(ull t) {
    float lo, hi; upk2(t, lo, hi);
    return pk2(fmaxf(lo, 0.f), fmaxf(hi, 0.f));
}

// ---------------- Layer 1: in_c = 1 (tiny) ----------------
__global__ void layer1_kernel(const float* __restrict__ x,
                              const float* __restrict__ ea,
                              const float* __restrict__ w,
                              const float* __restrict__ b,
                              const float* __restrict__ root,
                              const float* __restrict__ bias) {
    int n = blockIdx.x;
    int o = threadIdx.x;          // 0..511
    __shared__ float4 sc[NN-1];
    __shared__ float  sxs[NN-1];
    if (o < NN-1) {
        int k = o;
        int s = k + (k >= n);
        sc[k]  = *reinterpret_cast<const float4*>(ea + edge_id(s, n)*4);
        sxs[k] = x[s];
    }
    __syncthreads();
    float w0 = w[o], w1 = w[D1+o], w2 = w[2*D1+o], w3 = w[3*D1+o];
    float bb = b[o];
    float acc = 0.f;
    #pragma unroll
    for (int k = 0; k < NN-1; k++) {
        float4 c = sc[k];
        float t = fmaf(c.x, w0, fmaf(c.y, w1, fmaf(c.z, w2, fmaf(c.w, w3, bb))));
        acc = fmaf(sxs[k], fmaxf(t, 0.f), acc);
    }
    float v = acc * (1.f/34.f) + x[n]*root[o] + bias[o];
    g_h1[n*D1+o] = fmaxf(v, 0.f);
}

// ---------------- Layer 2 edge/message kernel ----------------
// grid (NN, NS2), 256 threads; thread owns output o = tid, f32x2 packs edge PAIRS
__global__ void __launch_bounds__(256, 3)
l2edge_kernel(const float* __restrict__ ea,
              const float* __restrict__ w,    // [4, D1*D2]
              const float* __restrict__ b,    // [D1*D2]
              const float* __restrict__ root) // [D1, D2]
{
    int n  = blockIdx.x;
    int cs = blockIdx.y;
    int tid = threadIdx.x;      // = o
    int ibase = cs*ICH2;

    __shared__ float scx[4*SXW];        // transposed coeffs: scx[v*SXW + k]
    __shared__ float sx[ICH2*SXW];      // sx[i*SXW + k] = h1[s_k, ibase+i]; k=34 -> node n

    if (tid < NN-1) {
        int k = tid, s = k + (k >= n);
        float4 c = *reinterpret_cast<const float4*>(ea + edge_id(s, n)*4);
        scx[0*SXW + k] = c.x; scx[1*SXW + k] = c.y;
        scx[2*SXW + k] = c.z; scx[3*SXW + k] = c.w;
    }
    for (int idx = tid; idx < NN*ICH2; idx += 256) {
        int k = idx / ICH2, i = idx % ICH2;
        int s = (k < NN-1) ? (k + (k >= n)) : n;
        sx[i*SXW + k] = g_h1[s*D1 + ibase + i];
    }
    __syncthreads();

    const int PL = D1*D2;
    ull acc = 0ull;
    float racc = 0.f;

    for (int i = 0; i < ICH2; i++) {
        int base = (ibase + i)*D2 + tid;
        float w0 = w[base], w1 = w[base + PL], w2 = w[base + 2*PL], w3 = w[base + 3*PL];
        float bb = b[base];
        float rr = root[base];
        float xn = sx[i*SXW + 34];
        racc = fmaf(xn, rr, racc);
        ull W0 = pk2(w0, w0), W1 = pk2(w1, w1), W2 = pk2(w2, w2), W3 = pk2(w3, w3);
        ull B  = pk2(bb, bb);
        const ull* cx = reinterpret_cast<const ull*>(scx);
        const ull* xr = reinterpret_cast<const ull*>(&sx[i*SXW]);
        #pragma unroll
        for (int kp = 0; kp < 17; kp++) {
            ull t = fma2(cx[kp],            W0, B);
            t     = fma2(cx[SXW/2 + kp],   W1, t);
            t     = fma2(cx[SXW   + kp],   W2, t);
            t     = fma2(cx[3*SXW/2 + kp], W3, t);
            t     = relu2(t);
            acc   = fma2(xr[kp], t, acc);
        }
    }

    float alo, ahi;
    upk2(acc, alo, ahi);
    g_p2[cs][n*D2 + tid] = (alo + ahi)*(1.f/34.f) + racc;
}

__global__ void fin2_kernel(const float* __restrict__ bias) {
    int idx = blockIdx.x*blockDim.x + threadIdx.x;
    if (idx >= NN*D2) return;
    float s = 0.f;
    #pragma unroll
    for (int p = 0; p < NS2; p++) s += g_p2[p][idx];
    g_h2[idx] = fmaxf(s + bias[idx % D2], 0.f);
}

// ---------------- Layer 3 edge/message kernel ----------------
// grid (NN, NS3), 128 threads; same edge-pair packing
__global__ void __launch_bounds__(128, 6)
l3edge_kernel(const float* __restrict__ ea,
              const float* __restrict__ w,    // [4, D2*D3]
              const float* __restrict__ b,    // [D2*D3]
              const float* __restrict__ root) // [D2, D3]
{
    int n  = blockIdx.x;
    int cs = blockIdx.y;
    int tid = threadIdx.x;      // = o
    int ibase = cs*ICH3;

    __shared__ float scx[4*SXW];
    __shared__ float sx[ICH3*SXW];

    if (tid < NN-1) {
        int k = tid, s = k + (k >= n);
        float4 c = *reinterpret_cast<const float4*>(ea + edge_id(s, n)*4);
        scx[0*SXW + k] = c.x; scx[1*SXW + k] = c.y;
        scx[2*SXW + k] = c.z; scx[3*SXW + k] = c.w;
    }
    for (int idx = tid; idx < NN*ICH3; idx += 128) {
        int k = idx / ICH3, i = idx % ICH3;
        int s = (k < NN-1) ? (k + (k >= n)) : n;
        sx[i*SXW + k] = g_h2[s*D2 + ibase + i];
    }
    __syncthreads();

    const int PL = D2*D3;
    ull acc = 0ull;
    float racc = 0.f;

    for (int i = 0; i < ICH3; i++) {
        int base = (ibase + i)*D3 + tid;
        float w0 = w[base], w1 = w[base + PL], w2 = w[base + 2*PL], w3 = w[base + 3*PL];
        float bb = b[base];
        float rr = root[base];
        float xn = sx[i*SXW + 34];
        racc = fmaf(xn, rr, racc);
        ull W0 = pk2(w0, w0), W1 = pk2(w1, w1), W2 = pk2(w2, w2), W3 = pk2(w3, w3);
        ull B  = pk2(bb, bb);
        const ull* cx = reinterpret_cast<const ull*>(scx);
        const ull* xr = reinterpret_cast<const ull*>(&sx[i*SXW]);
        #pragma unroll
        for (int kp = 0; kp < 17; kp++) {
            ull t = fma2(cx[kp],            W0, B);
            t     = fma2(cx[SXW/2 + kp],   W1, t);
            t     = fma2(cx[SXW   + kp],   W2, t);
            t     = fma2(cx[3*SXW/2 + kp], W3, t);
            t     = relu2(t);
            acc   = fma2(xr[kp], t, acc);
        }
    }

    float alo, ahi;
    upk2(acc, alo, ahi);
    g_p3[cs][n*D3 + tid] = (alo + ahi)*(1.f/34.f) + racc;
}

__global__ void fin3_kernel(const float* __restrict__ bias) {
    int idx = blockIdx.x*blockDim.x + threadIdx.x;
    if (idx >= NN*D3) return;
    float s = 0.f;
    #pragma unroll
    for (int p = 0; p < NS3; p++) s += g_p3[p][idx];
    g_h3[idx] = fmaxf(s + bias[idx % D3], 0.f);
}

// ---------------- CBT output ----------------
__global__ void cbt_kernel(float* __restrict__ out) {
    int a = blockIdx.x;
    int tid = threadIdx.x;  // 128
    __shared__ float sa[D3];
    sa[tid] = g_h3[a*D3 + tid];
    __syncthreads();
    int warp = tid >> 5, lane = tid & 31;
    for (int i = warp; i < NN; i += 4) {
        float s = 0.f;
        #pragma unroll
        for (int q = 0; q < 4; q++) {
            int f = lane + q*32;
            s += fabsf(g_h3[i*D3 + f] - sa[f]);
        }
        #pragma unroll
        for (int off = 16; off; off >>= 1)
            s += __shfl_down_sync(0xffffffffu, s, off);
        if (lane == 0) out[a*NN + i] = s;
    }
}

extern "C" void kernel_launch(void* const* d_in, const int* in_sizes, int n_in,
                              void* d_out, int out_size) {
    const float* x   = (const float*)d_in[0];
    const float* ea  = (const float*)d_in[1];
    // d_in[2] = edge_index (unused; structure derived analytically)
    const float* m1w = (const float*)d_in[3];
    const float* m1b = (const float*)d_in[4];
    const float* r1  = (const float*)d_in[5];
    const float* b1  = (const float*)d_in[6];
    const float* m2w = (const float*)d_in[7];
    const float* m2b = (const float*)d_in[8];
    const float* r2  = (const float*)d_in[9];
    const float* b2  = (const float*)d_in[10];
    const float* m3w = (const float*)d_in[11];
    const float* m3b = (const float*)d_in[12];
    const float* r3  = (const float*)d_in[13];
    const float* b3  = (const float*)d_in[14];
    float* out = (float*)d_out;

    layer1_kernel<<<NN, D1>>>(x, ea, m1w, m1b, r1, b1);
    l2edge_kernel<<<dim3(NN, NS2), 256>>>(ea, m2w, m2b, r2);
    fin2_kernel<<<(NN*D2 + 255)/256, 256>>>(b2);
    l3edge_kernel<<<dim3(NN, NS3), 128>>>(ea, m3w, m3b, r3);
    fin3_kernel<<<(NN*D3 + 127)/128, 128>>>(b3);
    cbt_kernel<<<NN, D3>>>(out);
}

// round 6
// speedup vs baseline: 1.5877x; 1.5877x over previous
#include <cuda_runtime.h>

#define NN   35
#define D1   512
#define D2   256
#define D3   128
#define NS2  16
#define ICH2 (D1/NS2)   // 32
#define NS3  32
#define ICH3 (D2/NS3)   // 8

typedef unsigned long long ull;

__device__ __align__(16) float g_h1[NN*D1];
__device__ __align__(16) float g_h2[NN*D2];
__device__ __align__(16) float g_h3[NN*D3];
__device__ float g_p2[NS2][NN*D2];
__device__ float g_p3[NS3][NN*D3];

// COO is src-major, fully connected, no self-loops
__device__ __forceinline__ int edge_id(int s, int n) {
    return s*(NN-1) + (s < n ? n-1 : n);
}

// ---- packed f32x2 helpers ----
__device__ __forceinline__ ull fma2(ull a, ull b, ull c) {
    ull d;
    asm("fma.rn.f32x2 %0, %1, %2, %3;" : "=l"(d) : "l"(a), "l"(b), "l"(c));
    return d;
}
__device__ __forceinline__ ull pk2(float lo, float hi) {
    ull r; asm("mov.b64 %0, {%1,%2};" : "=l"(r) : "f"(lo), "f"(hi)); return r;
}
__device__ __forceinline__ void upk2(ull v, float& lo, float& hi) {
    asm("mov.b64 {%0,%1}, %2;" : "=f"(lo), "=f"(hi) : "l"(v));
}
__device__ __forceinline__ ull relu2(ull t) {
    float lo, hi; upk2(t, lo, hi);
    return pk2(fmaxf(lo, 0.f), fmaxf(hi, 0.f));
}

// ---------------- Layer 1: in_c = 1 (tiny) ----------------
__global__ void layer1_kernel(const float* __restrict__ x,
                              const float* __restrict__ ea,
                              const float* __restrict__ w,
                              const float* __restrict__ b,
                              const float* __restrict__ root,
                              const float* __restrict__ bias) {
    int n = blockIdx.x;
    int o = threadIdx.x;          // 0..511
    __shared__ float4 sc[NN-1];
    __shared__ float  sxs[NN-1];
    if (o < NN-1) {
        int k = o;
        int s = k + (k >= n);
        sc[k]  = *reinterpret_cast<const float4*>(ea + edge_id(s, n)*4);
        sxs[k] = x[s];
    }
    __syncthreads();
    float w0 = w[o], w1 = w[D1+o], w2 = w[2*D1+o], w3 = w[3*D1+o];
    float bb = b[o];
    float acc = 0.f;
    #pragma unroll
    for (int k = 0; k < NN-1; k++) {
        float4 c = sc[k];
        float t = fmaf(c.x, w0, fmaf(c.y, w1, fmaf(c.z, w2, fmaf(c.w, w3, bb))));
        acc = fmaf(sxs[k], fmaxf(t, 0.f), acc);
    }
    float v = acc * (1.f/34.f) + x[n]*root[o] + bias[o];
    g_h1[n*D1+o] = fmaxf(v, 0.f);
}

// ---------------- Layer 2 edge/message kernel ----------------
// grid (NN, NS2), 256 threads; thread owns output o = tid.
// f32x2 packs INPUT-FEATURE pairs (i, i+1); 2 independent chains per k.
__global__ void __launch_bounds__(256, 3)
l2edge_kernel(const float* __restrict__ ea,
              const float* __restrict__ w,    // [4, D1*D2]
              const float* __restrict__ b,    // [D1*D2]
              const float* __restrict__ root) // [D1, D2]
{
    int n  = blockIdx.x;
    int cs = blockIdx.y;
    int tid = threadIdx.x;      // = o
    int ibase = cs*ICH2;

    __shared__ __align__(16) ulonglong2 scA[NN-1], scB[NN-1]; // dup'd coeffs
    __shared__ __align__(16) float sx[NN*ICH2];               // k-major: sx[k*ICH2+i]; k=34 -> node n

    if (tid < NN-1) {
        int k = tid, s = k + (k >= n);
        float4 c = *reinterpret_cast<const float4*>(ea + edge_id(s, n)*4);
        scA[k] = make_ulonglong2(pk2(c.x, c.x), pk2(c.y, c.y));
        scB[k] = make_ulonglong2(pk2(c.z, c.z), pk2(c.w, c.w));
    }
    {
        ull* sxq = reinterpret_cast<ull*>(sx);
        const ull* hq = reinterpret_cast<const ull*>(g_h1);
        for (int idx = tid; idx < NN*(ICH2/2); idx += 256) {
            int k = idx >> 4, ip = idx & 15;           // ICH2/2 = 16
            int s = (k < NN-1) ? (k + (k >= n)) : n;
            sxq[idx] = hq[(s*D1 + ibase)/2 + ip];
        }
    }
    __syncthreads();

    const int PL = D1*D2;
    const ull* sxq = reinterpret_cast<const ull*>(sx);
    ull acc0 = 0ull, acc1 = 0ull, racc = 0ull;

    for (int ib = 0; ib < ICH2/4; ib++) {
        int i0 = ibase + ib*4;
        int a0 = i0*D2 + tid, a1 = a0 + D2, a2 = a0 + 2*D2, a3 = a0 + 3*D2;
        // weight pairs: chain0 covers (i0,i0+1), chain1 covers (i0+2,i0+3)
        ull W00 = pk2(w[a0       ], w[a1       ]);
        ull W01 = pk2(w[a0 +   PL], w[a1 +   PL]);
        ull W02 = pk2(w[a0 + 2*PL], w[a1 + 2*PL]);
        ull W03 = pk2(w[a0 + 3*PL], w[a1 + 3*PL]);
        ull W10 = pk2(w[a2       ], w[a3       ]);
        ull W11 = pk2(w[a2 +   PL], w[a3 +   PL]);
        ull W12 = pk2(w[a2 + 2*PL], w[a3 + 2*PL]);
        ull W13 = pk2(w[a2 + 3*PL], w[a3 + 3*PL]);
        ull B0  = pk2(b[a0], b[a1]);
        ull B1  = pk2(b[a2], b[a3]);
        ull R0  = pk2(root[a0], root[a1]);
        ull R1  = pk2(root[a2], root[a3]);

        int xb = (NN-1)*(ICH2/2) + ib*2;
        racc = fma2(sxq[xb],     R0, racc);
        racc = fma2(sxq[xb + 1], R1, racc);

        #pragma unroll 2
        for (int k = 0; k < NN-1; k++) {
            ulonglong2 cA = scA[k];
            ulonglong2 cB = scB[k];
            int xk = k*(ICH2/2) + ib*2;
            ull t0 = fma2(cA.x, W00, B0);
            ull t1 = fma2(cA.x, W10, B1);
            t0 = fma2(cA.y, W01, t0);
            t1 = fma2(cA.y, W11, t1);
            t0 = fma2(cB.x, W02, t0);
            t1 = fma2(cB.x, W12, t1);
            t0 = fma2(cB.y, W03, t0);
            t1 = fma2(cB.y, W13, t1);
            t0 = relu2(t0);
            t1 = relu2(t1);
            acc0 = fma2(sxq[xk],     t0, acc0);
            acc1 = fma2(sxq[xk + 1], t1, acc1);
        }
    }

    float a0l, a0h, a1l, a1h, rl, rh;
    upk2(acc0, a0l, a0h);
    upk2(acc1, a1l, a1h);
    upk2(racc, rl, rh);
    g_p2[cs][n*D2 + tid] = (a0l + a0h + a1l + a1h)*(1.f/34.f) + rl + rh;
}

__global__ void fin2_kernel(const float* __restrict__ bias) {
    int idx = blockIdx.x*blockDim.x + threadIdx.x;
    if (idx >= NN*D2) return;
    float s = 0.f;
    #pragma unroll
    for (int p = 0; p < NS2; p++) s += g_p2[p][idx];
    g_h2[idx] = fmaxf(s + bias[idx % D2], 0.f);
}

// ---------------- Layer 3 edge/message kernel ----------------
// grid (NN, NS3), 128 threads; same i-pair packing, ICH3 = 8 -> 2 i-blocks
__global__ void __launch_bounds__(128, 8)
l3edge_kernel(const float* __restrict__ ea,
              const float* __restrict__ w,    // [4, D2*D3]
              const float* __restrict__ b,    // [D2*D3]
              const float* __restrict__ root) // [D2, D3]
{
    int n  = blockIdx.x;
    int cs = blockIdx.y;
    int tid = threadIdx.x;      // = o
    int ibase = cs*ICH3;

    __shared__ __align__(16) ulonglong2 scA[NN-1], scB[NN-1];
    __shared__ __align__(16) float sx[NN*ICH3];

    if (tid < NN-1) {
        int k = tid, s = k + (k >= n);
        float4 c = *reinterpret_cast<const float4*>(ea + edge_id(s, n)*4);
        scA[k] = make_ulonglong2(pk2(c.x, c.x), pk2(c.y, c.y));
        scB[k] = make_ulonglong2(pk2(c.z, c.z), pk2(c.w, c.w));
    }
    {
        ull* sxq = reinterpret_cast<ull*>(sx);
        const ull* hq = reinterpret_cast<const ull*>(g_h2);
        for (int idx = tid; idx < NN*(ICH3/2); idx += 128) {
            int k = idx >> 2, ip = idx & 3;            // ICH3/2 = 4
            int s = (k < NN-1) ? (k + (k >= n)) : n;
            sxq[idx] = hq[(s*D2 + ibase)/2 + ip];
        }
    }
    __syncthreads();

    const int PL = D2*D3;
    const ull* sxq = reinterpret_cast<const ull*>(sx);
    ull acc0 = 0ull, acc1 = 0ull, racc = 0ull;

    #pragma unroll
    for (int ib = 0; ib < ICH3/4; ib++) {
        int i0 = ibase + ib*4;
        int a0 = i0*D3 + tid, a1 = a0 + D3, a2 = a0 + 2*D3, a3 = a0 + 3*D3;
        ull W00 = pk2(w[a0       ], w[a1       ]);
        ull W01 = pk2(w[a0 +   PL], w[a1 +   PL]);
        ull W02 = pk2(w[a0 + 2*PL], w[a1 + 2*PL]);
        ull W03 = pk2(w[a0 + 3*PL], w[a1 + 3*PL]);
        ull W10 = pk2(w[a2       ], w[a3       ]);
        ull W11 = pk2(w[a2 +   PL], w[a3 +   PL]);
        ull W12 = pk2(w[a2 + 2*PL], w[a3 + 2*PL]);
        ull W13 = pk2(w[a2 + 3*PL], w[a3 + 3*PL]);
        ull B0  = pk2(b[a0], b[a1]);
        ull B1  = pk2(b[a2], b[a3]);
        ull R0  = pk2(root[a0], root[a1]);
        ull R1  = pk2(root[a2], root[a3]);

        int xb = (NN-1)*(ICH3/2) + ib*2;
        racc = fma2(sxq[xb],     R0, racc);
        racc = fma2(sxq[xb + 1], R1, racc);

        #pragma unroll 2
        for (int k = 0; k < NN-1; k++) {
            ulonglong2 cA = scA[k];
            ulonglong2 cB = scB[k];
            int xk = k*(ICH3/2) + ib*2;
            ull t0 = fma2(cA.x, W00, B0);
            ull t1 = fma2(cA.x, W10, B1);
            t0 = fma2(cA.y, W01, t0);
            t1 = fma2(cA.y, W11, t1);
            t0 = fma2(cB.x, W02, t0);
            t1 = fma2(cB.x, W12, t1);
            t0 = fma2(cB.y, W03, t0);
            t1 = fma2(cB.y, W13, t1);
            t0 = relu2(t0);
            t1 = relu2(t1);
            acc0 = fma2(sxq[xk],     t0, acc0);
            acc1 = fma2(sxq[xk + 1], t1, acc1);
        }
    }

    float a0l, a0h, a1l, a1h, rl, rh;
    upk2(acc0, a0l, a0h);
    upk2(acc1, a1l, a1h);
    upk2(racc, rl, rh);
    g_p3[cs][n*D3 + tid] = (a0l + a0h + a1l + a1h)*(1.f/34.f) + rl + rh;
}

__global__ void fin3_kernel(const float* __restrict__ bias) {
    int idx = blockIdx.x*blockDim.x + threadIdx.x;
    if (idx >= NN*D3) return;
    float s = 0.f;
    #pragma unroll
    for (int p = 0; p < NS3; p++) s += g_p3[p][idx];
    g_h3[idx] = fmaxf(s + bias[idx % D3], 0.f);
}

// ---------------- CBT output ----------------
__global__ void cbt_kernel(float* __restrict__ out) {
    int a = blockIdx.x;
    int tid = threadIdx.x;  // 128
    __shared__ float sa[D3];
    sa[tid] = g_h3[a*D3 + tid];
    __syncthreads();
    int warp = tid >> 5, lane = tid & 31;
    for (int i = warp; i < NN; i += 4) {
        float s = 0.f;
        #pragma unroll
        for (int q = 0; q < 4; q++) {
            int f = lane + q*32;
            s += fabsf(g_h3[i*D3 + f] - sa[f]);
        }
        #pragma unroll
        for (int off = 16; off; off >>= 1)
            s += __shfl_down_sync(0xffffffffu, s, off);
        if (lane == 0) out[a*NN + i] = s;
    }
}

extern "C" void kernel_launch(void* const* d_in, const int* in_sizes, int n_in,
                              void* d_out, int out_size) {
    const float* x   = (const float*)d_in[0];
    const float* ea  = (const float*)d_in[1];
    // d_in[2] = edge_index (unused; structure derived analytically)
    const float* m1w = (const float*)d_in[3];
    const float* m1b = (const float*)d_in[4];
    const float* r1  = (const float*)d_in[5];
    const float* b1  = (const float*)d_in[6];
    const float* m2w = (const float*)d_in[7];
    const float* m2b = (const float*)d_in[8];
    const float* r2  = (const float*)d_in[9];
    const float* b2  = (const float*)d_in[10];
    const float* m3w = (const float*)d_in[11];
    const float* m3b = (const float*)d_in[12];
    const float* r3  = (const float*)d_in[13];
    const float* b3  = (const float*)d_in[14];
    float* out = (float*)d_out;

    layer1_kernel<<<NN, D1>>>(x, ea, m1w, m1b, r1, b1);
    l2edge_kernel<<<dim3(NN, NS2), 256>>>(ea, m2w, m2b, r2);
    fin2_kernel<<<(NN*D2 + 255)/256, 256>>>(b2);
    l3edge_kernel<<<dim3(NN, NS3), 128>>>(ea, m3w, m3b, r3);
    fin3_kernel<<<(NN*D3 + 127)/128, 128>>>(b3);
    cbt_kernel<<<NN, D3>>>(out);
}

// round 8
// speedup vs baseline: 1.8115x; 1.1410x over previous
#include <cuda_runtime.h>

#define NN   35
#define D1   512
#define D2   256
#define D3   128
#define ICH  8
#define NP   (ICH/2)      // 4 i-pairs per block
#define NS2  (D1/ICH)     // 64
#define NS3  (D2/ICH)     // 32

typedef unsigned long long ull;

__device__ __align__(16) float g_h1[NN*D1];
__device__ __align__(16) float g_h2[NN*D2];
__device__ __align__(16) float g_h3[NN*D3];
__device__ float g_p2[NS2][NN*D2];
__device__ float g_p3[NS3][NN*D3];

// COO is src-major, fully connected, no self-loops
__device__ __forceinline__ int edge_id(int s, int n) {
    return s*(NN-1) + (s < n ? n-1 : n);
}

// ---- packed f32x2 helpers ----
__device__ __forceinline__ ull fma2(ull a, ull b, ull c) {
    ull d;
    asm("fma.rn.f32x2 %0, %1, %2, %3;" : "=l"(d) : "l"(a), "l"(b), "l"(c));
    return d;
}
__device__ __forceinline__ ull pk2(float lo, float hi) {
    ull r; asm("mov.b64 %0, {%1,%2};" : "=l"(r) : "f"(lo), "f"(hi)); return r;
}
__device__ __forceinline__ void upk2(ull v, float& lo, float& hi) {
    asm("mov.b64 {%0,%1}, %2;" : "=f"(lo), "=f"(hi) : "l"(v));
}
__device__ __forceinline__ ull relu2(ull t) {
    float lo, hi; upk2(t, lo, hi);
    return pk2(fmaxf(lo, 0.f), fmaxf(hi, 0.f));
}

// ---------------- Layer 1: in_c = 1 (tiny) ----------------
__global__ void layer1_kernel(const float* __restrict__ x,
                              const float* __restrict__ ea,
                              const float* __restrict__ w,
                              const float* __restrict__ b,
                              const float* __restrict__ root,
                              const float* __restrict__ bias) {
    int n = blockIdx.x;
    int o = threadIdx.x;          // 0..511
    __shared__ float4 sc[NN-1];
    __shared__ float  sxs[NN-1];
    if (o < NN-1) {
        int k = o;
        int s = k + (k >= n);
        sc[k]  = *reinterpret_cast<const float4*>(ea + edge_id(s, n)*4);
        sxs[k] = x[s];
    }
    __syncthreads();
    float w0 = w[o], w1 = w[D1+o], w2 = w[2*D1+o], w3 = w[3*D1+o];
    float bb = b[o];
    float acc = 0.f;
    #pragma unroll
    for (int k = 0; k < NN-1; k++) {
        float4 c = sc[k];
        float t = fmaf(c.x, w0, fmaf(c.y, w1, fmaf(c.z, w2, fmaf(c.w, w3, bb))));
        acc = fmaf(sxs[k], fmaxf(t, 0.f), acc);
    }
    float v = acc * (1.f/34.f) + x[n]*root[o] + bias[o];
    g_h1[n*D1+o] = fmaxf(v, 0.f);
}

// ---------------- Generic edge/message kernel ----------------
// grid (NN, DIN/ICH), DOUT threads; thread owns output o = tid.
// k-OUTER loop; all 4 i-pair chains (ICH=8 inputs) held in registers.
template<int DIN, int DOUT, int MB>
__global__ void __launch_bounds__(DOUT, MB)
edge_kernel(const float* __restrict__ ea,
            const float* __restrict__ w,    // [4, DIN*DOUT]
            const float* __restrict__ b,    // [DIN*DOUT]
            const float* __restrict__ root, // [DIN, DOUT]
            const float* __restrict__ hin,  // [NN, DIN]
            float* __restrict__ part)       // [NS][NN*DOUT] flattened
{
    int n  = blockIdx.x;
    int cs = blockIdx.y;
    int tid = threadIdx.x;      // = o
    int ibase = cs*ICH;

    __shared__ __align__(16) ulonglong2 scA[NN-1], scB[NN-1];
    __shared__ __align__(16) ull sxq[NN*NP];  // k-major: sxq[k*NP+ip]; k=34 -> node n

    if (tid < NN-1) {
        int k = tid, s = k + (k >= n);
        float4 c = *reinterpret_cast<const float4*>(ea + edge_id(s, n)*4);
        scA[k] = make_ulonglong2(pk2(c.x, c.x), pk2(c.y, c.y));
        scB[k] = make_ulonglong2(pk2(c.z, c.z), pk2(c.w, c.w));
    }
    {
        const ull* hq = reinterpret_cast<const ull*>(hin);
        for (int idx = tid; idx < NN*NP; idx += DOUT) {
            int k = idx >> 2, ip = idx & 3;
            int s = (k < NN-1) ? (k + (k >= n)) : n;
            sxq[idx] = hq[(s*DIN + ibase)/2 + ip];
        }
    }
    __syncthreads();

    constexpr int PL = DIN*DOUT;
    ull W[NP][4], Bp[NP], Rp[NP], acc[NP];
    #pragma unroll
    for (int ip = 0; ip < NP; ip++) {
        int a = (ibase + 2*ip)*DOUT + tid;
        W[ip][0] = pk2(w[a       ], w[a        + DOUT]);
        W[ip][1] = pk2(w[a +   PL], w[a +   PL + DOUT]);
        W[ip][2] = pk2(w[a + 2*PL], w[a + 2*PL + DOUT]);
        W[ip][3] = pk2(w[a + 3*PL], w[a + 3*PL + DOUT]);
        Bp[ip]   = pk2(b[a], b[a + DOUT]);
        Rp[ip]   = pk2(root[a], root[a + DOUT]);
        acc[ip]  = 0ull;
    }
    ull racc = 0ull;
    #pragma unroll
    for (int ip = 0; ip < NP; ip++)
        racc = fma2(sxq[(NN-1)*NP + ip], Rp[ip], racc);

    #pragma unroll 2
    for (int k = 0; k < NN-1; k++) {
        ulonglong2 cA = scA[k];
        ulonglong2 cB = scB[k];
        const ulonglong2* xr = reinterpret_cast<const ulonglong2*>(&sxq[k*NP]);
        ulonglong2 x01 = xr[0], x23 = xr[1];
        ull xv[NP] = {x01.x, x01.y, x23.x, x23.y};
        #pragma unroll
        for (int ip = 0; ip < NP; ip++) {
            ull t = fma2(cA.x, W[ip][0], Bp[ip]);
            t = fma2(cA.y, W[ip][1], t);
            t = fma2(cB.x, W[ip][2], t);
            t = fma2(cB.y, W[ip][3], t);
            t = relu2(t);
            acc[ip] = fma2(xv[ip], t, acc[ip]);
        }
    }

    float s0 = 0.f;
    #pragma unroll
    for (int ip = 0; ip < NP; ip++) {
        float lo, hi; upk2(acc[ip], lo, hi);
        s0 += lo + hi;
    }
    float rl, rh; upk2(racc, rl, rh);
    part[cs*(NN*DOUT) + n*DOUT + tid] = s0*(1.f/34.f) + rl + rh;
}

// ---------------- finalize: sum partials + bias + relu ----------------
template<int NS, int DOUT>
__global__ void fin_kernel(const float* __restrict__ part,
                           const float* __restrict__ bias,
                           float* __restrict__ hout) {
    int idx = blockIdx.x*blockDim.x + threadIdx.x;
    if (idx >= NN*DOUT) return;
    float s = 0.f;
    #pragma unroll
    for (int p = 0; p < NS; p++) s += part[p*(NN*DOUT) + idx];
    hout[idx] = fmaxf(s + bias[idx % DOUT], 0.f);
}

// ---------------- CBT output ----------------
__global__ void cbt_kernel(float* __restrict__ out) {
    int a = blockIdx.x;
    int tid = threadIdx.x;  // 128
    __shared__ float sa[D3];
    sa[tid] = g_h3[a*D3 + tid];
    __syncthreads();
    int warp = tid >> 5, lane = tid & 31;
    for (int i = warp; i < NN; i += 4) {
        float s = 0.f;
        #pragma unroll
        for (int q = 0; q < 4; q++) {
            int f = lane + q*32;
            s += fabsf(g_h3[i*D3 + f] - sa[f]);
        }
        #pragma unroll
        for (int off = 16; off; off >>= 1)
            s += __shfl_down_sync(0xffffffffu, s, off);
        if (lane == 0) out[a*NN + i] = s;
    }
}

extern "C" void kernel_launch(void* const* d_in, const int* in_sizes, int n_in,
                              void* d_out, int out_size) {
    const float* x   = (const float*)d_in[0];
    const float* ea  = (const float*)d_in[1];
    // d_in[2] = edge_index (unused; structure derived analytically)
    const float* m1w = (const float*)d_in[3];
    const float* m1b = (const float*)d_in[4];
    const float* r1  = (const float*)d_in[5];
    const float* b1  = (const float*)d_in[6];
    const float* m2w = (const float*)d_in[7];
    const float* m2b = (const float*)d_in[8];
    const float* r2  = (const float*)d_in[9];
    const float* b2  = (const float*)d_in[10];
    const float* m3w = (const float*)d_in[11];
    const float* m3b = (const float*)d_in[12];
    const float* r3  = (const float*)d_in[13];
    const float* b3  = (const float*)d_in[14];
    float* out = (float*)d_out;

    // device-symbol addresses MUST come from cudaGetSymbolAddress on host
    void *h1v, *h2v, *h3v, *p2v, *p3v;
    cudaGetSymbolAddress(&h1v, g_h1);
    cudaGetSymbolAddress(&h2v, g_h2);
    cudaGetSymbolAddress(&h3v, g_h3);
    cudaGetSymbolAddress(&p2v, g_p2);
    cudaGetSymbolAddress(&p3v, g_p3);
    float* h1 = (float*)h1v; float* h2 = (float*)h2v; float* h3 = (float*)h3v;
    float* p2 = (float*)p2v; float* p3 = (float*)p3v;

    layer1_kernel<<<NN, D1>>>(x, ea, m1w, m1b, r1, b1);
    edge_kernel<D1, D2, 2><<<dim3(NN, NS2), D2>>>(ea, m2w, m2b, r2, h1, p2);
    fin_kernel<NS2, D2><<<(NN*D2 + 255)/256, 256>>>(p2, b2, h2);
    edge_kernel<D2, D3, 4><<<dim3(NN, NS3), D3>>>(ea, m3w, m3b, r3, h2, p3);
    fin_kernel<NS3, D3><<<(NN*D3 + 127)/128, 128>>>(p3, b3, h3);
    cbt_kernel<<<NN, D3>>>(out);
}